// round 15
// baseline (speedup 1.0000x reference)
#include <cuda_runtime.h>
#include <cuda_bf16.h>
#include <stdint.h>

#define B_ 4096
#define L_ 200
#define E_ 128
#define F_ 64
#define NI_ 100000
#define TI_ROWS 100096
#define LDF 72
#define LDK 136
#define PREP_SMEM ((16*128 + 2*128*132)*4)

__device__ __align__(16) __nv_bfloat16 g_w1f[E_*LDF];
__device__ __align__(16) __nv_bfloat16 g_w2f[E_*LDK];
__device__ __align__(16) __nv_bfloat16 g_w1c[E_*LDK];
__device__ __align__(16) __nv_bfloat16 g_ti[(size_t)TI_ROWS*E_];
__device__ float g_cu[B_*E_];
__device__ float g_c2u[B_*E_];

// slim smem: weights + ONE aliased activation buffer (fx/comp) + misc  => ~108.5KB, 2 CTAs/SM
struct __align__(16) SmemMain {
    __nv_bfloat16 w1f[E_*LDF];
    __nv_bfloat16 w2f[E_*LDK];
    __nv_bfloat16 w1c[E_*LDK];
    __nv_bfloat16 fxc[64*LDK];
    float user[E_], cu[E_], c2u[E_], fb2[E_], w2v[E_];
    float part[4][64];
    float logits[256];
    float red[8];
    float scal[2];
    int   ids[256];
};

// ---------------- PTX helpers ----------------
__device__ __forceinline__ uint32_t su32(const void* p) {
    return (uint32_t)__cvta_generic_to_shared(p);
}
__device__ __forceinline__ void ldsm4(uint32_t r[4], uint32_t a) {
    asm volatile("ldmatrix.sync.aligned.m8n8.x4.shared.b16 {%0,%1,%2,%3},[%4];"
        : "=r"(r[0]), "=r"(r[1]), "=r"(r[2]), "=r"(r[3]) : "r"(a));
}
__device__ __forceinline__ void mma16816(float* d, const uint32_t* a, const uint32_t* b) {
    asm volatile(
        "mma.sync.aligned.m16n8k16.row.col.f32.bf16.bf16.f32 "
        "{%0,%1,%2,%3},{%4,%5,%6,%7},{%8,%9},{%0,%1,%2,%3};\n"
        : "+f"(d[0]), "+f"(d[1]), "+f"(d[2]), "+f"(d[3])
        : "r"(a[0]), "r"(a[1]), "r"(a[2]), "r"(a[3]), "r"(b[0]), "r"(b[1]));
}

// ---- 32x32 warp tile from smem (A and B) ----
template<int NK>
__device__ __forceinline__ void gemm_lm(uint32_t aB, int lda2, uint32_t bB, int ldb2,
                                        float acc[2][4][4]) {
    #pragma unroll
    for (int ks = 0; ks < NK; ks++) {
        uint32_t a0[4], a1[4], p[4], q[4];
        ldsm4(a0, aB + ks*32);
        ldsm4(a1, aB + 16*lda2 + ks*32);
        ldsm4(p,  bB + ks*32);
        ldsm4(q,  bB + 16*ldb2 + ks*32);
        uint32_t bj[4][2] = {{p[0], p[2]}, {p[1], p[3]}, {q[0], q[2]}, {q[1], q[3]}};
        #pragma unroll
        for (int j = 0; j < 4; j++) {
            mma16816(acc[0][j], a0, bj[j]);
            mma16816(acc[1][j], a1, bj[j]);
        }
    }
}
__device__ __forceinline__ void zero_acc(float acc[2][4][4]) {
    #pragma unroll
    for (int t = 0; t < 2; t++)
        #pragma unroll
        for (int j = 0; j < 4; j++)
            #pragma unroll
            for (int i = 0; i < 4; i++) acc[t][j][i] = 0.f;
}

// ---- GEMM1: A-fragments straight from gmem (fp32 feat -> bf16 regs), B from smem ----
__device__ __forceinline__ void gemm1_g(const float* __restrict__ fb, int rowbase,
                                        uint32_t bB, float acc[2][4][4], int g, int t4) {
    #pragma unroll
    for (int ks = 0; ks < 4; ks++) {
        const int k0 = ks*16 + t4*2;
        uint32_t a[2][4];
        #pragma unroll
        for (int t = 0; t < 2; t++) {
            const int l0 = rowbase + t*16 + g;
            const int l1 = l0 + 8;
            float2 v00, v01, v10, v11;
            if (l0 < L_) {
                const float* f0 = fb + (size_t)l0*F_ + k0;
                v00 = *(const float2*)f0; v01 = *(const float2*)(f0 + 8);
            } else { v00 = make_float2(0.f,0.f); v01 = make_float2(0.f,0.f); }
            if (l1 < L_) {
                const float* f1 = fb + (size_t)l1*F_ + k0;
                v10 = *(const float2*)f1; v11 = *(const float2*)(f1 + 8);
            } else { v10 = make_float2(0.f,0.f); v11 = make_float2(0.f,0.f); }
            __nv_bfloat162 c0 = __floats2bfloat162_rn(v00.x, v00.y);
            __nv_bfloat162 c1 = __floats2bfloat162_rn(v10.x, v10.y);
            __nv_bfloat162 c2 = __floats2bfloat162_rn(v01.x, v01.y);
            __nv_bfloat162 c3 = __floats2bfloat162_rn(v11.x, v11.y);
            a[t][0] = *(uint32_t*)&c0; a[t][1] = *(uint32_t*)&c1;
            a[t][2] = *(uint32_t*)&c2; a[t][3] = *(uint32_t*)&c3;
        }
        uint32_t p[4], q[4];
        ldsm4(p, bB + ks*32);
        ldsm4(q, bB + 16*(LDF*2) + ks*32);
        uint32_t bj[4][2] = {{p[0],p[2]},{p[1],p[3]},{q[0],q[2]},{q[1],q[3]}};
        #pragma unroll
        for (int j = 0; j < 4; j++) {
            mma16816(acc[0][j], a[0], bj[j]);
            mma16816(acc[1][j], a[1], bj[j]);
        }
    }
}

__device__ __forceinline__ void epi_store(const float acc[2][4][4],
                                          const float* __restrict__ addv,
                                          __nv_bfloat16* __restrict__ sOut,
                                          int wm, int wn, int g, int t4) {
    #pragma unroll
    for (int t = 0; t < 2; t++) {
        const int r0 = wm*32 + t*16 + g;
        #pragma unroll
        for (int j = 0; j < 4; j++) {
            const int c = wn*32 + j*8 + t4*2;
            const float a0 = addv[c], a1 = addv[c+1];
            __nv_bfloat162 v01 = __floats2bfloat162_rn(fmaxf(acc[t][j][0] + a0, 0.f),
                                                       fmaxf(acc[t][j][1] + a1, 0.f));
            __nv_bfloat162 v23 = __floats2bfloat162_rn(fmaxf(acc[t][j][2] + a0, 0.f),
                                                       fmaxf(acc[t][j][3] + a1, 0.f));
            *(__nv_bfloat162*)(sOut + r0*LDK + c) = v01;
            *(__nv_bfloat162*)(sOut + (r0+8)*LDK + c) = v23;
        }
    }
}

__device__ __forceinline__ void copyw(void* dst, const void* src, int bytes, int tid) {
    uint4* d = (uint4*)dst;
    const uint4* s = (const uint4*)src;
    const int n = bytes >> 4;
    for (int i = tid; i < n; i += 256) d[i] = s[i];
}

// ---------------- prep_ti (verified, unchanged) ----------------
__global__ void __launch_bounds__(256) prep_ti(
    const float* __restrict__ item_emb, const float* __restrict__ fw1,
    const float* __restrict__ fw2, const float* __restrict__ w1) {
    extern __shared__ __nv_bfloat16 sm[];
    __nv_bfloat16* w1i_s  = sm;
    __nv_bfloat16* items_s = sm + 128*LDK;
    const int tid = threadIdx.x;
    const int lane = tid & 31, wid = tid >> 5;
    const int wm = wid & 1, wn = wid >> 1;
    const int g = lane >> 2, t4 = lane & 3;
    const int rl = lane & 15, hk = lane >> 4;

    {
        int j = blockIdx.x*256 + tid;
        if (j < 128*64) {
            int n = j >> 6, k = j & 63;
            g_w1f[n*LDF + k] = __float2bfloat16_rn(fw1[n*192 + 128 + k]);
        } else if (j < 128*64 + 128*128) {
            int i = j - 128*64, n = i >> 7, k = i & 127;
            g_w2f[n*LDK + k] = __float2bfloat16_rn(fw2[n*128 + k]);
        } else if (j < 128*64 + 2*128*128) {
            int i = j - 128*64 - 128*128, n = i >> 7, k = i & 127;
            g_w1c[n*LDK + k] = __float2bfloat16_rn(w1[n*384 + 256 + k]);
        }
    }
    for (int i = tid; i < 128*128; i += 256) {
        int n = i >> 7, k = i & 127;
        w1i_s[n*LDK + k] = __float2bfloat16_rn(w1[n*384 + 128 + k]);
    }

    const uint32_t aB = su32(items_s) + (wm*32 + rl)*(LDK*2) + hk*16;
    const uint32_t bB = su32(w1i_s)   + (wn*32 + rl)*(LDK*2) + hk*16;

    for (int sub = 0; sub < 2; sub++) {
        const int i0 = blockIdx.x * 256 + sub * 128;
        __syncthreads();
        for (int i = tid; i < 128*32; i += 256) {
            int r = i >> 5, q = i & 31;
            float4 v = make_float4(0.f, 0.f, 0.f, 0.f);
            if (i0 + r < NI_) v = ((const float4*)item_emb)[(size_t)(i0 + r)*32 + q];
            __nv_bfloat162 v01 = __floats2bfloat162_rn(v.x, v.y);
            __nv_bfloat162 v23 = __floats2bfloat162_rn(v.z, v.w);
            uint2 u; u.x = *(uint32_t*)&v01; u.y = *(uint32_t*)&v23;
            *(uint2*)((char*)items_s + r*(LDK*2) + q*8) = u;
        }
        __syncthreads();
        #pragma unroll
        for (int half = 0; half < 2; half++) {
            float acc[2][4][4];
            zero_acc(acc);
            gemm_lm<8>(aB + half*64*(LDK*2), LDK*2, bB, LDK*2, acc);
            #pragma unroll
            for (int t = 0; t < 2; t++) {
                const int r0 = half*64 + wm*32 + t*16 + g;
                #pragma unroll
                for (int j = 0; j < 4; j++) {
                    const int c = wn*32 + j*8 + t4*2;
                    __nv_bfloat162 v01 = __floats2bfloat162_rn(acc[t][j][0], acc[t][j][1]);
                    __nv_bfloat162 v23 = __floats2bfloat162_rn(acc[t][j][2], acc[t][j][3]);
                    if (i0 + r0 < NI_)
                        *(__nv_bfloat162*)(g_ti + (size_t)(i0 + r0)*E_ + c) = v01;
                    if (i0 + r0 + 8 < NI_)
                        *(__nv_bfloat162*)(g_ti + (size_t)(i0 + r0 + 8)*E_ + c) = v23;
                }
            }
        }
    }
}

// ---------------- prep_user (verified, unchanged) ----------------
__global__ void __launch_bounds__(256) prep_user(
    const int* __restrict__ user_ids, const float* __restrict__ user_emb,
    const float* __restrict__ fw1, const float* __restrict__ w1,
    const float* __restrict__ fb1, const float* __restrict__ b1v) {
    extern __shared__ float smf[];
    float* su  = smf;
    float* wt1 = smf + 16*128;
    float* wt2 = wt1 + 128*132;
    const int tid = threadIdx.x;
    const int b0 = blockIdx.x * 16;
    for (int i = tid; i < 16*128; i += 256) {
        int bl = i >> 7, f = i & 127;
        su[i] = user_emb[(size_t)user_ids[b0 + bl] * E_ + f];
    }
    for (int i = tid; i < 128*128; i += 256) {
        int n = i >> 7, f = i & 127;
        wt1[f*132 + n] = fw1[n*192 + f];
        wt2[f*132 + n] = w1[n*384 + f];
    }
    __syncthreads();
    const int m = tid >> 7, n = tid & 127;
    const float* wt = m ? wt2 : wt1;
    const float bias = m ? b1v[n] : fb1[n];
    float* gout = m ? g_c2u : g_cu;
    for (int bl = 0; bl < 16; bl++) {
        float acc = bias;
        const float* u = su + bl*128;
        #pragma unroll 8
        for (int f = 0; f < 128; f++) acc += u[f] * wt[f*132 + n];
        gout[(size_t)(b0 + bl) * E_ + n] = acc;
    }
}

__device__ __forceinline__ float block_reduce(float v, bool do_max, SmemMain* s, int tid) {
    #pragma unroll
    for (int o = 16; o > 0; o >>= 1) {
        float u = __shfl_xor_sync(0xffffffffu, v, o);
        v = do_max ? fmaxf(v, u) : (v + u);
    }
    if ((tid & 31) == 0) s->red[tid >> 5] = v;
    __syncthreads();
    if (tid == 0) {
        float r = s->red[0];
        #pragma unroll
        for (int i = 1; i < 8; i++) r = do_max ? fmaxf(r, s->red[i]) : (r + s->red[i]);
        s->scal[0] = r;
    }
    __syncthreads();
    return s->scal[0];
}

// ---------------- main: 256 thr/CTA, 2 CTAs/SM, 2x4 grid, 32x32 tiles, 64-row M-tiles ----------------
__global__ void __launch_bounds__(256, 2) main_kernel(
    const int* __restrict__ user_ids, const int* __restrict__ item_ids,
    const float* __restrict__ features, const float* __restrict__ user_emb,
    const float* __restrict__ item_emb, const float* __restrict__ feat_b2,
    const float* __restrict__ w2, const float* __restrict__ b2,
    float* __restrict__ out) {
    extern __shared__ char smraw[];
    SmemMain* s = (SmemMain*)smraw;
    const int tid = threadIdx.x;
    const int lane = tid & 31, wid = tid >> 5;
    const int wm = wid & 1, wn = wid >> 1;
    const int g = lane >> 2, t4 = lane & 3;
    const int rl = lane & 15, hk = lane >> 4;

    copyw(s->w1f, g_w1f, (int)sizeof(g_w1f), tid);
    copyw(s->w2f, g_w2f, (int)sizeof(g_w2f), tid);
    copyw(s->w1c, g_w1c, (int)sizeof(g_w1c), tid);
    if (tid < E_) { s->fb2[tid] = feat_b2[tid]; s->w2v[tid] = w2[tid]; }
    const float b2v = b2[0];

    const uint32_t bF = su32(s->w1f) + (wn*32 + rl)*(LDF*2) + hk*16;
    const uint32_t aX = su32(s->fxc) + (wm*32 + rl)*(LDK*2) + hk*16;
    const uint32_t b2f= su32(s->w2f) + (wn*32 + rl)*(LDK*2) + hk*16;
    const uint32_t bC = su32(s->w1c) + (wn*32 + rl)*(LDK*2) + hk*16;

    for (int b = blockIdx.x; b < B_; b += gridDim.x) {
        __syncthreads();
        if (tid < E_) {
            s->user[tid] = user_emb[(size_t)user_ids[b] * E_ + tid];
            s->cu[tid]   = g_cu[(size_t)b * E_ + tid];
            s->c2u[tid]  = g_c2u[(size_t)b * E_ + tid];
        }
        s->ids[tid] = (tid < L_) ? item_ids[b*L_ + tid] : 0;
        __syncthreads();

        const float* featb = features + (size_t)b * L_ * F_;

        for (int tile = 0; tile < 4; tile++) {
            const int base = tile * 64;
            float acc[2][4][4];

            // GEMM1: fx = relu(cu + feat @ w1f^T), K=64 ; A direct from gmem
            zero_acc(acc);
            gemm1_g(featb, base + wm*32, bF, acc, g, t4);
            epi_store(acc, s->cu, s->fxc, wm, wn, g, t4);     // fx
            __syncthreads();

            // GEMM2: comp = relu(fb2 + fx @ w2f^T), K=128 (comp aliases fx)
            zero_acc(acc);
            gemm_lm<8>(aX, LDK*2, b2f, LDK*2, acc);
            __syncthreads();                                   // all fx reads done
            epi_store(acc, s->fb2, s->fxc, wm, wn, g, t4);     // comp
            __syncthreads();

            // GEMM3: h = relu(c2u + ti + comp @ w1c^T); logit = w2.h + b2
            zero_acc(acc);
            gemm_lm<8>(aX, LDK*2, bC, LDK*2, acc);
            #pragma unroll
            for (int t = 0; t < 2; t++) {
                const int r0 = wm*32 + t*16 + g;
                const int l0 = base + r0, l1 = l0 + 8;
                const int id0 = s->ids[l0], id1 = s->ids[l1];
                float p0 = 0.f, p1 = 0.f;
                #pragma unroll
                for (int j = 0; j < 4; j++) {
                    const int c = wn*32 + j*8 + t4*2;
                    const float a0 = s->c2u[c], a1 = s->c2u[c+1];
                    const float q0 = s->w2v[c], q1 = s->w2v[c+1];
                    uint32_t u0 = __ldg((const uint32_t*)(g_ti + (size_t)id0*E_ + c));
                    uint32_t u1 = __ldg((const uint32_t*)(g_ti + (size_t)id1*E_ + c));
                    __nv_bfloat162 t0 = *(__nv_bfloat162*)&u0;
                    __nv_bfloat162 t1 = *(__nv_bfloat162*)&u1;
                    p0 += fmaxf(acc[t][j][0] + a0 + __bfloat162float(t0.x), 0.f)*q0
                        + fmaxf(acc[t][j][1] + a1 + __bfloat162float(t0.y), 0.f)*q1;
                    p1 += fmaxf(acc[t][j][2] + a0 + __bfloat162float(t1.x), 0.f)*q0
                        + fmaxf(acc[t][j][3] + a1 + __bfloat162float(t1.y), 0.f)*q1;
                }
                p0 += __shfl_xor_sync(0xffffffffu, p0, 1);
                p0 += __shfl_xor_sync(0xffffffffu, p0, 2);
                p1 += __shfl_xor_sync(0xffffffffu, p1, 1);
                p1 += __shfl_xor_sync(0xffffffffu, p1, 2);
                if (t4 == 0) {
                    s->part[wn][r0]     = p0;
                    s->part[wn][r0 + 8] = p1;
                }
            }
            __syncthreads();
            if (tid < 64)
                s->logits[base + tid] = b2v + s->part[0][tid] + s->part[1][tid]
                                            + s->part[2][tid] + s->part[3][tid];
        }
        __syncthreads();

        // softmax over L=200
        float mv = -3.4e38f;
        for (int i = tid; i < L_; i += 256) mv = fmaxf(mv, s->logits[i]);
        mv = block_reduce(mv, true, s, tid);
        float sv = 0.f;
        for (int i = tid; i < L_; i += 256) {
            float e = __expf(s->logits[i] - mv);
            s->logits[i] = e;
            sv += e;
        }
        sv = block_reduce(sv, false, s, tid);
        const float inv = 1.f / sv;

        // out = user + sum_l attn_l * items_l (fp32 re-gather, L2-resident)
        const int e = tid & 127, half = tid >> 7;
        float accv = 0.f;
        for (int l = half; l < L_; l += 2)
            accv += s->logits[l] * __ldg(item_emb + (size_t)s->ids[l]*E_ + e);
        float* pbuf = &s->part[0][0];
        if (half) pbuf[e] = accv;
        __syncthreads();
        if (!half)
            out[(size_t)b*E_ + e] = s->user[e] + (accv + pbuf[e]) * inv;
    }
}

extern "C" void kernel_launch(void* const* d_in, const int* in_sizes, int n_in,
                              void* d_out, int out_size) {
    const int*   user_ids = (const int*)d_in[0];
    const int*   item_ids = (const int*)d_in[1];
    const float* features = (const float*)d_in[2];
    const float* user_emb = (const float*)d_in[3];
    const float* item_emb = (const float*)d_in[4];
    const float* feat_w1  = (const float*)d_in[5];
    const float* feat_b1  = (const float*)d_in[6];
    const float* feat_w2  = (const float*)d_in[7];
    const float* feat_b2  = (const float*)d_in[8];
    const float* w1       = (const float*)d_in[9];
    const float* b1       = (const float*)d_in[10];
    const float* w2       = (const float*)d_in[11];
    const float* b2       = (const float*)d_in[12];
    float* out = (float*)d_out;

    const int ti_smem = 2 * 128 * LDK * 2;
    cudaFuncSetAttribute(prep_ti, cudaFuncAttributeMaxDynamicSharedMemorySize, ti_smem);
    cudaFuncSetAttribute(prep_user, cudaFuncAttributeMaxDynamicSharedMemorySize, PREP_SMEM);
    cudaFuncSetAttribute(main_kernel, cudaFuncAttributeMaxDynamicSharedMemorySize,
                         (int)sizeof(SmemMain));
    int nsm = 148;
    cudaDeviceGetAttribute(&nsm, cudaDevAttrMultiProcessorCount, 0);

    prep_ti<<<(NI_ + 255) / 256, 256, ti_smem>>>(item_emb, feat_w1, feat_w2, w1);
    prep_user<<<256, 256, PREP_SMEM>>>(user_ids, user_emb, feat_w1, w1, feat_b1, b1);
    main_kernel<<<nsm * 2, 256, sizeof(SmemMain)>>>(user_ids, item_ids, features, user_emb,
                                                    item_emb, feat_b2, w2, b2, out);
}

// round 17
// speedup vs baseline: 1.1255x; 1.1255x over previous
#include <cuda_runtime.h>
#include <cuda_bf16.h>
#include <stdint.h>

#define B_ 4096
#define L_ 200
#define E_ 128
#define F_ 64
#define NI_ 100000
#define TI_ROWS 100096
#define LDF 72
#define LDK 136
#define PREP_SMEM ((16*128 + 2*128*132)*4)
#define NT 512

__device__ __align__(16) __nv_bfloat16 g_w1f[E_*LDF];
__device__ __align__(16) __nv_bfloat16 g_w2f[E_*LDK];
__device__ __align__(16) __nv_bfloat16 g_w1c[E_*LDK];
__device__ __align__(16) __nv_bfloat16 g_ti[(size_t)TI_ROWS*E_];
__device__ float g_cu[B_*E_];
__device__ float g_c2u[B_*E_];

struct __align__(16) SmemMain {
    __nv_bfloat16 w1f[E_*LDF];
    __nv_bfloat16 w2f[E_*LDK];
    __nv_bfloat16 w1c[E_*LDK];
    __nv_bfloat16 feat[128*LDF];
    __nv_bfloat16 ti[128*LDK];
    __nv_bfloat16 fx[128*LDK];
    __nv_bfloat16 comp[128*LDK];
    float user[E_], cu[E_], c2u[E_], fb2[E_], w2v[E_];
    float part[4][128];
    float logits[256];
    float red[16];
    float scal[2];
    int   ids[256];
};

// ---------------- PTX helpers ----------------
__device__ __forceinline__ uint32_t su32(const void* p) {
    return (uint32_t)__cvta_generic_to_shared(p);
}
__device__ __forceinline__ void ldsm4(uint32_t r[4], uint32_t a) {
    asm volatile("ldmatrix.sync.aligned.m8n8.x4.shared.b16 {%0,%1,%2,%3},[%4];"
        : "=r"(r[0]), "=r"(r[1]), "=r"(r[2]), "=r"(r[3]) : "r"(a));
}
__device__ __forceinline__ void mma16816(float* d, const uint32_t* a, const uint32_t* b) {
    asm volatile(
        "mma.sync.aligned.m16n8k16.row.col.f32.bf16.bf16.f32 "
        "{%0,%1,%2,%3},{%4,%5,%6,%7},{%8,%9},{%0,%1,%2,%3};\n"
        : "+f"(d[0]), "+f"(d[1]), "+f"(d[2]), "+f"(d[3])
        : "r"(a[0]), "r"(a[1]), "r"(a[2]), "r"(a[3]), "r"(b[0]), "r"(b[1]));
}
__device__ __forceinline__ void cpa16(uint32_t dst, const void* src) {
    asm volatile("cp.async.cg.shared.global [%0], [%1], 16;"
        :: "r"(dst), "l"(src) : "memory");
}
#define CP_COMMIT() asm volatile("cp.async.commit_group;" ::: "memory")
#define CP_WAIT0()  asm volatile("cp.async.wait_group 0;" ::: "memory")
// group barrier: 128 threads of row-group wm (barrier ids 1..4; 0 is __syncthreads)
__device__ __forceinline__ void barg(int wm) {
    asm volatile("bar.sync %0, 128;" :: "r"(wm + 1) : "memory");
}

// ---- 32x32 warp tile: 4 LDSM + 8 MMA per k-slice ----
template<int NK>
__device__ __forceinline__ void gemm_lm(uint32_t aB, int lda2, uint32_t bB, int ldb2,
                                        float acc[2][4][4]) {
    #pragma unroll
    for (int ks = 0; ks < NK; ks++) {
        uint32_t a0[4], a1[4], p[4], q[4];
        ldsm4(a0, aB + ks*32);
        ldsm4(a1, aB + 16*lda2 + ks*32);
        ldsm4(p,  bB + ks*32);
        ldsm4(q,  bB + 16*ldb2 + ks*32);
        uint32_t bj[4][2] = {{p[0], p[2]}, {p[1], p[3]}, {q[0], q[2]}, {q[1], q[3]}};
        #pragma unroll
        for (int j = 0; j < 4; j++) {
            mma16816(acc[0][j], a0, bj[j]);
            mma16816(acc[1][j], a1, bj[j]);
        }
    }
}
__device__ __forceinline__ void zero_acc(float acc[2][4][4]) {
    #pragma unroll
    for (int t = 0; t < 2; t++)
        #pragma unroll
        for (int j = 0; j < 4; j++)
            #pragma unroll
            for (int i = 0; i < 4; i++) acc[t][j][i] = 0.f;
}

__device__ __forceinline__ void epi_store(const float acc[2][4][4],
                                          const float* __restrict__ addv,
                                          __nv_bfloat16* __restrict__ sOut,
                                          int wm, int wn, int g, int t4) {
    #pragma unroll
    for (int t = 0; t < 2; t++) {
        const int r0 = wm*32 + t*16 + g;
        #pragma unroll
        for (int j = 0; j < 4; j++) {
            const int c = wn*32 + j*8 + t4*2;
            const float a0 = addv[c], a1 = addv[c+1];
            __nv_bfloat162 v01 = __floats2bfloat162_rn(fmaxf(acc[t][j][0] + a0, 0.f),
                                                       fmaxf(acc[t][j][1] + a1, 0.f));
            __nv_bfloat162 v23 = __floats2bfloat162_rn(fmaxf(acc[t][j][2] + a0, 0.f),
                                                       fmaxf(acc[t][j][3] + a1, 0.f));
            *(__nv_bfloat162*)(sOut + r0*LDK + c) = v01;
            *(__nv_bfloat162*)(sOut + (r0+8)*LDK + c) = v23;
        }
    }
}

__device__ __forceinline__ void copyw(void* dst, const void* src, int bytes, int tid, int nt) {
    uint4* d = (uint4*)dst;
    const uint4* s = (const uint4*)src;
    const int n = bytes >> 4;
    for (int i = tid; i < n; i += nt) d[i] = s[i];
}

// ---------------- prep_ti (verified, unchanged) ----------------
__global__ void __launch_bounds__(256) prep_ti(
    const float* __restrict__ item_emb, const float* __restrict__ fw1,
    const float* __restrict__ fw2, const float* __restrict__ w1) {
    extern __shared__ __nv_bfloat16 sm[];
    __nv_bfloat16* w1i_s  = sm;
    __nv_bfloat16* items_s = sm + 128*LDK;
    const int tid = threadIdx.x;
    const int lane = tid & 31, wid = tid >> 5;
    const int wm = wid & 1, wn = wid >> 1;
    const int g = lane >> 2, t4 = lane & 3;
    const int rl = lane & 15, hk = lane >> 4;

    {
        int j = blockIdx.x*256 + tid;
        if (j < 128*64) {
            int n = j >> 6, k = j & 63;
            g_w1f[n*LDF + k] = __float2bfloat16_rn(fw1[n*192 + 128 + k]);
        } else if (j < 128*64 + 128*128) {
            int i = j - 128*64, n = i >> 7, k = i & 127;
            g_w2f[n*LDK + k] = __float2bfloat16_rn(fw2[n*128 + k]);
        } else if (j < 128*64 + 2*128*128) {
            int i = j - 128*64 - 128*128, n = i >> 7, k = i & 127;
            g_w1c[n*LDK + k] = __float2bfloat16_rn(w1[n*384 + 256 + k]);
        }
    }
    for (int i = tid; i < 128*128; i += 256) {
        int n = i >> 7, k = i & 127;
        w1i_s[n*LDK + k] = __float2bfloat16_rn(w1[n*384 + 128 + k]);
    }

    const uint32_t aB = su32(items_s) + (wm*32 + rl)*(LDK*2) + hk*16;
    const uint32_t bB = su32(w1i_s)   + (wn*32 + rl)*(LDK*2) + hk*16;

    for (int sub = 0; sub < 2; sub++) {
        const int i0 = blockIdx.x * 256 + sub * 128;
        __syncthreads();
        for (int i = tid; i < 128*32; i += 256) {
            int r = i >> 5, q = i & 31;
            float4 v = make_float4(0.f, 0.f, 0.f, 0.f);
            if (i0 + r < NI_) v = ((const float4*)item_emb)[(size_t)(i0 + r)*32 + q];
            __nv_bfloat162 v01 = __floats2bfloat162_rn(v.x, v.y);
            __nv_bfloat162 v23 = __floats2bfloat162_rn(v.z, v.w);
            uint2 u; u.x = *(uint32_t*)&v01; u.y = *(uint32_t*)&v23;
            *(uint2*)((char*)items_s + r*(LDK*2) + q*8) = u;
        }
        __syncthreads();
        #pragma unroll
        for (int half = 0; half < 2; half++) {
            float acc[2][4][4];
            zero_acc(acc);
            gemm_lm<8>(aB + half*64*(LDK*2), LDK*2, bB, LDK*2, acc);
            #pragma unroll
            for (int t = 0; t < 2; t++) {
                const int r0 = half*64 + wm*32 + t*16 + g;
                #pragma unroll
                for (int j = 0; j < 4; j++) {
                    const int c = wn*32 + j*8 + t4*2;
                    __nv_bfloat162 v01 = __floats2bfloat162_rn(acc[t][j][0], acc[t][j][1]);
                    __nv_bfloat162 v23 = __floats2bfloat162_rn(acc[t][j][2], acc[t][j][3]);
                    if (i0 + r0 < NI_)
                        *(__nv_bfloat162*)(g_ti + (size_t)(i0 + r0)*E_ + c) = v01;
                    if (i0 + r0 + 8 < NI_)
                        *(__nv_bfloat162*)(g_ti + (size_t)(i0 + r0 + 8)*E_ + c) = v23;
                }
            }
        }
    }
}

// ---------------- prep_user (verified, unchanged) ----------------
__global__ void __launch_bounds__(256) prep_user(
    const int* __restrict__ user_ids, const float* __restrict__ user_emb,
    const float* __restrict__ fw1, const float* __restrict__ w1,
    const float* __restrict__ fb1, const float* __restrict__ b1v) {
    extern __shared__ float smf[];
    float* su  = smf;
    float* wt1 = smf + 16*128;
    float* wt2 = wt1 + 128*132;
    const int tid = threadIdx.x;
    const int b0 = blockIdx.x * 16;
    for (int i = tid; i < 16*128; i += 256) {
        int bl = i >> 7, f = i & 127;
        su[i] = user_emb[(size_t)user_ids[b0 + bl] * E_ + f];
    }
    for (int i = tid; i < 128*128; i += 256) {
        int n = i >> 7, f = i & 127;
        wt1[f*132 + n] = fw1[n*192 + f];
        wt2[f*132 + n] = w1[n*384 + f];
    }
    __syncthreads();
    const int m = tid >> 7, n = tid & 127;
    const float* wt = m ? wt2 : wt1;
    const float bias = m ? b1v[n] : fb1[n];
    float* gout = m ? g_c2u : g_cu;
    for (int bl = 0; bl < 16; bl++) {
        float acc = bias;
        const float* u = su + bl*128;
        #pragma unroll 8
        for (int f = 0; f < 128; f++) acc += u[f] * wt[f*132 + n];
        gout[(size_t)(b0 + bl) * E_ + n] = acc;
    }
}

__device__ __forceinline__ float block_reduce(float v, bool do_max, SmemMain* s, int tid) {
    #pragma unroll
    for (int o = 16; o > 0; o >>= 1) {
        float u = __shfl_xor_sync(0xffffffffu, v, o);
        v = do_max ? fmaxf(v, u) : (v + u);
    }
    if ((tid & 31) == 0) s->red[tid >> 5] = v;
    __syncthreads();
    if (tid == 0) {
        float r = s->red[0];
        #pragma unroll
        for (int i = 1; i < 16; i++) r = do_max ? fmaxf(r, s->red[i]) : (r + s->red[i]);
        s->scal[0] = r;
    }
    __syncthreads();
    return s->scal[0];
}

// ---- main: 512 thr, 4 independent row-groups (named barriers), 32x32 warp tiles ----
// group wm = tid>>7 owns rows wm*32..wm*32+31 of each 128-row tile;
// its 4 warps sit on SMSPs 0..3 (wid&3), so every SMSP interleaves 4 groups.
__global__ void __launch_bounds__(NT, 1) main_kernel(
    const int* __restrict__ user_ids, const int* __restrict__ item_ids,
    const float* __restrict__ features, const float* __restrict__ user_emb,
    const float* __restrict__ item_emb, const float* __restrict__ feat_b2,
    const float* __restrict__ w2, const float* __restrict__ b2,
    float* __restrict__ out) {
    extern __shared__ char smraw[];
    SmemMain* s = (SmemMain*)smraw;
    const int tid = threadIdx.x;
    const int lane = tid & 31, wid = tid >> 5;
    const int wm = wid >> 2, wn = wid & 3;          // group = 4 consecutive warps
    const int gt = tid & 127;                        // thread index within group
    const int g = lane >> 2, t4 = lane & 3;
    const int rl = lane & 15, hk = lane >> 4;

    copyw(s->w1f, g_w1f, (int)sizeof(g_w1f), tid, NT);
    copyw(s->w2f, g_w2f, (int)sizeof(g_w2f), tid, NT);
    copyw(s->w1c, g_w1c, (int)sizeof(g_w1c), tid, NT);
    if (tid < E_) { s->fb2[tid] = feat_b2[tid]; s->w2v[tid] = w2[tid]; }
    const float b2v = b2[0];

    const uint32_t tiB = su32(s->ti);
    const uint32_t aF = su32(s->feat) + (wm*32 + rl)*(LDF*2) + hk*16;
    const uint32_t bF = su32(s->w1f)  + (wn*32 + rl)*(LDF*2) + hk*16;
    const uint32_t aX = su32(s->fx)   + (wm*32 + rl)*(LDK*2) + hk*16;
    const uint32_t b2f= su32(s->w2f)  + (wn*32 + rl)*(LDK*2) + hk*16;
    const uint32_t aC = su32(s->comp) + (wm*32 + rl)*(LDK*2) + hk*16;
    const uint32_t bC = su32(s->w1c)  + (wn*32 + rl)*(LDK*2) + hk*16;

    for (int b = blockIdx.x; b < B_; b += gridDim.x) {
        __syncthreads();   // previous row fully done (logits/ids/part reuse)
        if (tid < E_) {
            s->user[tid] = user_emb[(size_t)user_ids[b] * E_ + tid];
            s->cu[tid]   = g_cu[(size_t)b * E_ + tid];
            s->c2u[tid]  = g_c2u[(size_t)b * E_ + tid];
        }
        if (tid < 256) s->ids[tid] = (tid < L_) ? item_ids[b*L_ + tid] : 0;
        __syncthreads();

        // per-group feat prefetch for tile 0 (group's 32 rows: 512 float4 / 128 thr)
        float4 pf[4];
        #pragma unroll
        for (int p = 0; p < 4; p++) {
            int i = gt + 128*p, r = wm*32 + (i >> 4), q = i & 15;
            pf[p] = (r < L_) ? ((const float4*)features)[(size_t)(b*L_ + r)*16 + q]
                             : make_float4(0.f, 0.f, 0.f, 0.f);
        }

        for (int tile = 0; tile < 2; tile++) {
            const int base = tile * 128;

            // group-local: ti cp.async + feat commit for rows wm*32..+31
            #pragma unroll
            for (int p = 0; p < 4; p++) {
                int i = gt + 128*p, r = wm*32 + (i >> 4), q = i & 15;
                int l = base + r;
                int id = (l < L_) ? s->ids[l] : 0;
                cpa16(tiB + r*(LDK*2) + q*16, (const char*)g_ti + (size_t)id*256 + q*16);
                __nv_bfloat162 v01 = __floats2bfloat162_rn(pf[p].x, pf[p].y);
                __nv_bfloat162 v23 = __floats2bfloat162_rn(pf[p].z, pf[p].w);
                uint2 u; u.x = *(uint32_t*)&v01; u.y = *(uint32_t*)&v23;
                *(uint2*)((char*)s->feat + r*(LDF*2) + q*8) = u;
            }
            CP_COMMIT();
            barg(wm);   // group's feat visible

            // prefetch next tile's feat behind this tile's GEMM chain
            if (tile == 0) {
                #pragma unroll
                for (int p = 0; p < 4; p++) {
                    int i = gt + 128*p, r = wm*32 + (i >> 4), q = i & 15;
                    int l = 128 + r;
                    pf[p] = (l < L_) ? ((const float4*)features)[(size_t)(b*L_ + l)*16 + q]
                                     : make_float4(0.f, 0.f, 0.f, 0.f);
                }
            }

            float acc[2][4][4];
            // GEMM1: fx = relu(cu + feat @ w1f^T), K=64
            zero_acc(acc);
            gemm_lm<4>(aF, LDF*2, bF, LDF*2, acc);
            epi_store(acc, s->cu, s->fx, wm, wn, g, t4);
            barg(wm);

            // GEMM2: comp = relu(fb2 + fx @ w2f^T), K=128
            zero_acc(acc);
            gemm_lm<8>(aX, LDK*2, b2f, LDK*2, acc);
            epi_store(acc, s->fb2, s->comp, wm, wn, g, t4);
            CP_WAIT0();   // group's ti resident
            barg(wm);

            // GEMM3: h = relu(c2u + ti + comp @ w1c^T); logit = w2.h + b2
            zero_acc(acc);
            gemm_lm<8>(aC, LDK*2, bC, LDK*2, acc);
            #pragma unroll
            for (int t = 0; t < 2; t++) {
                const int r0 = wm*32 + t*16 + g;
                float p0 = 0.f, p1 = 0.f;
                #pragma unroll
                for (int j = 0; j < 4; j++) {
                    const int c = wn*32 + j*8 + t4*2;
                    const float a0 = s->c2u[c], a1 = s->c2u[c+1];
                    const float q0 = s->w2v[c], q1 = s->w2v[c+1];
                    __nv_bfloat162 t0 = *(__nv_bfloat162*)(s->ti + r0*LDK + c);
                    __nv_bfloat162 t1 = *(__nv_bfloat162*)(s->ti + (r0+8)*LDK + c);
                    p0 += fmaxf(acc[t][j][0] + a0 + __bfloat162float(t0.x), 0.f)*q0
                        + fmaxf(acc[t][j][1] + a1 + __bfloat162float(t0.y), 0.f)*q1;
                    p1 += fmaxf(acc[t][j][2] + a0 + __bfloat162float(t1.x), 0.f)*q0
                        + fmaxf(acc[t][j][3] + a1 + __bfloat162float(t1.y), 0.f)*q1;
                }
                p0 += __shfl_xor_sync(0xffffffffu, p0, 1);
                p0 += __shfl_xor_sync(0xffffffffu, p0, 2);
                p1 += __shfl_xor_sync(0xffffffffu, p1, 1);
                p1 += __shfl_xor_sync(0xffffffffu, p1, 2);
                if (t4 == 0) {
                    s->part[wn][r0]     = p0;
                    s->part[wn][r0 + 8] = p1;
                }
            }
            barg(wm);
            if (gt < 32) {
                const int r = wm*32 + gt;
                s->logits[base + r] = b2v + s->part[0][r] + s->part[1][r]
                                          + s->part[2][r] + s->part[3][r];
            }
            // next tile's commit writes only group-owned rows; no cross-group sync needed
        }
        __syncthreads();   // all groups' logits ready

        // softmax over L=200
        float mv = -3.4e38f;
        for (int i = tid; i < L_; i += NT) mv = fmaxf(mv, s->logits[i]);
        mv = block_reduce(mv, true, s, tid);
        float sv = 0.f;
        for (int i = tid; i < L_; i += NT) {
            float e = __expf(s->logits[i] - mv);
            s->logits[i] = e;
            sv += e;
        }
        sv = block_reduce(sv, false, s, tid);
        const float inv = 1.f / sv;

        // out = user + sum_l attn_l * items_l (fp32 re-gather, L2-resident)
        const int e = tid & 127, quarter = tid >> 7;
        float accv = 0.f;
        for (int l = quarter; l < L_; l += 4)
            accv += s->logits[l] * __ldg(item_emb + (size_t)s->ids[l]*E_ + e);
        float* pbuf = &s->part[0][0];
        if (quarter) pbuf[(quarter - 1)*128 + e] = accv;
        __syncthreads();
        if (!quarter)
            out[(size_t)b*E_ + e] = s->user[e]
                + (accv + pbuf[e] + pbuf[128 + e] + pbuf[256 + e]) * inv;
    }
}

extern "C" void kernel_launch(void* const* d_in, const int* in_sizes, int n_in,
                              void* d_out, int out_size) {
    const int*   user_ids = (const int*)d_in[0];
    const int*   item_ids = (const int*)d_in[1];
    const float* features = (const float*)d_in[2];
    const float* user_emb = (const float*)d_in[3];
    const float* item_emb = (const float*)d_in[4];
    const float* feat_w1  = (const float*)d_in[5];
    const float* feat_b1  = (const float*)d_in[6];
    const float* feat_w2  = (const float*)d_in[7];
    const float* feat_b2  = (const float*)d_in[8];
    const float* w1       = (const float*)d_in[9];
    const float* b1       = (const float*)d_in[10];
    const float* w2       = (const float*)d_in[11];
    const float* b2       = (const float*)d_in[12];
    float* out = (float*)d_out;

    const int ti_smem = 2 * 128 * LDK * 2;
    cudaFuncSetAttribute(prep_ti, cudaFuncAttributeMaxDynamicSharedMemorySize, ti_smem);
    cudaFuncSetAttribute(prep_user, cudaFuncAttributeMaxDynamicSharedMemorySize, PREP_SMEM);
    cudaFuncSetAttribute(main_kernel, cudaFuncAttributeMaxDynamicSharedMemorySize,
                         (int)sizeof(SmemMain));
    int nsm = 148;
    cudaDeviceGetAttribute(&nsm, cudaDevAttrMultiProcessorCount, 0);

    prep_ti<<<(NI_ + 255) / 256, 256, ti_smem>>>(item_emb, feat_w1, feat_w2, w1);
    prep_user<<<256, 256, PREP_SMEM>>>(user_ids, user_emb, feat_w1, w1, feat_b1, b1);
    main_kernel<<<nsm, NT, sizeof(SmemMain)>>>(user_ids, item_ids, features, user_emb,
                                               item_emb, feat_b2, w2, b2, out);
}